// round 16
// baseline (speedup 1.0000x reference)
#include <cuda_runtime.h>
#include <cuda_bf16.h>
#include <stdint.h>
#include <cstdint>
#include <math.h>

#define Bdim 8
#define Nseq 1024
#define Ddim 512
#define Hn 8
#define DH 64
#define BN_ROWS (Bdim * Nseq)   // 8192
#define NBH (Bdim * Hn)         // 64
#define HROWS (NBH * Nseq)      // 65536 head-rows of DH

#define L2E2 2.0813689810056077f        // (log2 e)^2
#define NEG2L2 (-2.0f * L2E2)
#define EPS_SC (1e-8f * L2E2)

typedef unsigned int u32;
typedef __nv_bfloat16 bf16;
typedef __nv_bfloat162 bf162;

// ---------------- scratch (device globals; no allocation allowed) ------------
__device__ bf16  g_h[BN_ROWS * Ddim];        // LN1 output (bf16)
__device__ bf16  g_q[BN_ROWS * Ddim];        // [BH, N, DH] bf16
__device__ bf16  g_k[BN_ROWS * Ddim];
__device__ bf16  g_v[BN_ROWS * Ddim];
__device__ bf16  g_attnout[BN_ROWS * Ddim];  // [B, N, D] bf16
__device__ float g_y[BN_ROWS * Ddim];        // proj + residual, pre-LN2 (f32)
__device__ bf16  g_wb[4][Ddim * Ddim];       // bf16 copies of Wq,Wk,Wv,Wo
__device__ float g_q2[HROWS];                // ||q||^2 * L2E2 per head-row
__device__ float g_k2[HROWS];                // ||k||^2 * L2E2 per head-row

// ---------------- helpers -----------------------------------------------------
__device__ __forceinline__ u32 s2u(const void* p) {
    u32 a;
    asm("{ .reg .u64 t; cvta.to.shared.u64 t, %1; cvt.u32.u64 %0, t; }" : "=r"(a) : "l"(p));
    return a;
}
__device__ __forceinline__ void cpa16(u32 smem, const void* g) {
    asm volatile("cp.async.cg.shared.global [%0],[%1],16;" :: "r"(smem), "l"(g));
}
#define CP_COMMIT() asm volatile("cp.async.commit_group;")
#define CP_WAIT0()  asm volatile("cp.async.wait_group 0;")

__device__ __forceinline__ void ldsm4(u32* r, u32 addr) {
    asm volatile("ldmatrix.sync.aligned.m8n8.x4.shared.b16 {%0,%1,%2,%3},[%4];"
                 : "=r"(r[0]), "=r"(r[1]), "=r"(r[2]), "=r"(r[3]) : "r"(addr));
}
__device__ __forceinline__ void ldsm4t(u32* r, u32 addr) {
    asm volatile("ldmatrix.sync.aligned.m8n8.x4.trans.shared.b16 {%0,%1,%2,%3},[%4];"
                 : "=r"(r[0]), "=r"(r[1]), "=r"(r[2]), "=r"(r[3]) : "r"(addr));
}
__device__ __forceinline__ void mma16(float* c, const u32* a, const u32* b) {
    asm volatile(
        "mma.sync.aligned.m16n8k16.row.col.f32.bf16.bf16.f32 "
        "{%0,%1,%2,%3},{%4,%5,%6,%7},{%8,%9},{%0,%1,%2,%3};\n"
        : "+f"(c[0]), "+f"(c[1]), "+f"(c[2]), "+f"(c[3])
        : "r"(a[0]), "r"(a[1]), "r"(a[2]), "r"(a[3]), "r"(b[0]), "r"(b[1]));
}
__device__ __forceinline__ u32 aaddr(const bf16* base, int stride, int mm, int k, int lane) {
    int row = mm + (lane & 7) + (((lane >> 3) & 1) << 3);
    int col = k + ((lane >> 4) << 3);
    return s2u(base + row * stride + col);
}
__device__ __forceinline__ u32 baddr_k(const bf16* base, int stride, int n, int k, int lane) {
    int m = lane >> 3;
    int row = n + ((m >> 1) << 3) + (lane & 7);
    int col = k + ((m & 1) << 3);
    return s2u(base + row * stride + col);
}
__device__ __forceinline__ u32 baddr_t(const bf16* base, int stride, int k, int n, int lane) {
    int m = lane >> 3;
    int row = k + ((m & 1) << 3) + (lane & 7);
    int col = n + ((m >> 1) << 3);
    return s2u(base + row * stride + col);
}
__device__ __forceinline__ float2 b2f(u32 u) {
    bf162 h = *(bf162*)&u;
    return __bfloat1622float2(h);
}
__device__ __forceinline__ float sqrt_ap(float x) {
    float y;
    asm("sqrt.approx.f32 %0, %1;" : "=f"(y) : "f"(x));
    return y;
}
__device__ __forceinline__ float ex2_ap(float x) {
    float y;
    asm("ex2.approx.ftz.f32 %0, %1;" : "=f"(y) : "f"(x));
    return y;
}

// ---------------- weight f32->bf16 conversion ---------------------------------
__global__ void wconv_kernel(const float* __restrict__ w0, const float* __restrict__ w1,
                             const float* __restrict__ w2, const float* __restrict__ w3)
{
    const float* src = (blockIdx.y == 0) ? w0 : (blockIdx.y == 1) ? w1
                      : (blockIdx.y == 2) ? w2 : w3;
    bf16* dst = g_wb[blockIdx.y];
    int i = blockIdx.x * 256 + threadIdx.x;
    float4 v = ((const float4*)src)[i];
    bf162 lo = __floats2bfloat162_rn(v.x, v.y);
    bf162 hi = __floats2bfloat162_rn(v.z, v.w);
    uint2 pk = { *(u32*)&lo, *(u32*)&hi };
    ((uint2*)dst)[i] = pk;
}

// ---------------- LayerNorm: one WARP per row, shuffle-only reduction ----------
__device__ __forceinline__ void ln_warp_body(const float* __restrict__ in,
                                             const float* __restrict__ gamma,
                                             const float* __restrict__ beta,
                                             int row, int lane, float4 o[4])
{
    const float4* r = (const float4*)(in + (size_t)row * Ddim);
    float4 a[4];
    float s = 0.f, s2 = 0.f;
    #pragma unroll
    for (int i = 0; i < 4; i++) {
        a[i] = r[i * 32 + lane];
        s  += a[i].x + a[i].y + a[i].z + a[i].w;
        s2 += a[i].x*a[i].x + a[i].y*a[i].y + a[i].z*a[i].z + a[i].w*a[i].w;
    }
    #pragma unroll
    for (int off = 16; off; off >>= 1) {
        s  += __shfl_xor_sync(0xffffffffu, s,  off);
        s2 += __shfl_xor_sync(0xffffffffu, s2, off);
    }
    float mean = s * (1.0f / Ddim);
    float var  = s2 * (1.0f / Ddim) - mean * mean;
    float rstd = rsqrtf(var + 1e-5f);
    #pragma unroll
    for (int i = 0; i < 4; i++) {
        float4 g = ((const float4*)gamma)[i * 32 + lane];
        float4 b = ((const float4*)beta)[i * 32 + lane];
        o[i].x = (a[i].x - mean) * rstd * g.x + b.x;
        o[i].y = (a[i].y - mean) * rstd * g.y + b.y;
        o[i].z = (a[i].z - mean) * rstd * g.z + b.z;
        o[i].w = (a[i].w - mean) * rstd * g.w + b.w;
    }
}

__global__ void __launch_bounds__(256) ln_bf16_kernel(
    const float* __restrict__ in, const float* __restrict__ gamma,
    const float* __restrict__ beta, bf16* __restrict__ out)
{
    int lane = threadIdx.x & 31;
    int row = blockIdx.x * 8 + (threadIdx.x >> 5);
    float4 o[4];
    ln_warp_body(in, gamma, beta, row, lane, o);
    #pragma unroll
    for (int i = 0; i < 4; i++) {
        bf162 lo = __floats2bfloat162_rn(o[i].x, o[i].y);
        bf162 hi = __floats2bfloat162_rn(o[i].z, o[i].w);
        uint2 pk = { *(u32*)&lo, *(u32*)&hi };
        *(uint2*)(out + (size_t)row * Ddim + (i * 32 + lane) * 4) = pk;
    }
}

__global__ void __launch_bounds__(256) ln_f32_kernel(
    const float* __restrict__ in, const float* __restrict__ gamma,
    const float* __restrict__ beta, float* __restrict__ out)
{
    int lane = threadIdx.x & 31;
    int row = blockIdx.x * 8 + (threadIdx.x >> 5);
    float4 o[4];
    ln_warp_body(in, gamma, beta, row, lane, o);
    #pragma unroll
    for (int i = 0; i < 4; i++)
        ((float4*)(out + (size_t)row * Ddim))[i * 32 + lane] = o[i];
}

// ---------------- bf16 MMA GEMM core, cp.async double-buffered ----------------
#define AST 72
#define WST 136
#define GAS0 0
#define GAS1 18432
#define GWS0 36864
#define GWS1 54272
#define GBS  71680
#define Q2P  72192     // [128 rows][2 heads][2 halves] f32 = 2048 B
#define GEMM_SMEM 74240

__device__ __forceinline__ void gemm_load_stage(const bf16* __restrict__ A,
                                                const bf16* __restrict__ W,
                                                bf16* As, bf16* Ws,
                                                int m0, int n0, int k0, int t)
{
    #pragma unroll
    for (int i = 0; i < 4; i++) {
        int f = t + 256 * i;
        int r = f >> 3, c = (f & 7) * 8;
        cpa16(s2u(As + r * AST + c), A + (size_t)(m0 + r) * Ddim + k0 + c);
    }
    #pragma unroll
    for (int i = 0; i < 4; i++) {
        int f = t + 256 * i;
        int r = f >> 4, c = (f & 15) * 8;
        cpa16(s2u(Ws + r * WST + c), W + (size_t)(k0 + r) * Ddim + n0 + c);
    }
    CP_COMMIT();
}

__device__ __forceinline__ void gemm_pipe_body(const bf16* __restrict__ A,
                                               const bf16* __restrict__ W,
                                               float acc[4][4][4],
                                               char* smraw)
{
    bf16* Asb[2] = { (bf16*)(smraw + GAS0), (bf16*)(smraw + GAS1) };
    bf16* Wsb[2] = { (bf16*)(smraw + GWS0), (bf16*)(smraw + GWS1) };
    const int t = threadIdx.x, lane = t & 31, wid = t >> 5;
    const int wm = (wid >> 2) * 64, wn = (wid & 3) * 32;
    const int m0 = blockIdx.y * 128, n0 = blockIdx.x * 128;

    #pragma unroll
    for (int i = 0; i < 4; i++)
        #pragma unroll
        for (int j = 0; j < 4; j++)
            #pragma unroll
            for (int c = 0; c < 4; c++) acc[i][j][c] = 0.f;

    gemm_load_stage(A, W, Asb[0], Wsb[0], m0, n0, 0, t);

    for (int kc = 0; kc < 8; kc++) {
        bf16* As = Asb[kc & 1];
        bf16* Ws = Wsb[kc & 1];
        CP_WAIT0();
        __syncthreads();
        if (kc < 7)
            gemm_load_stage(A, W, Asb[(kc + 1) & 1], Wsb[(kc + 1) & 1],
                            m0, n0, (kc + 1) * 64, t);
        #pragma unroll
        for (int ks = 0; ks < 4; ks++) {
            int kk = ks * 16;
            u32 a[4][4], b[4][2];
            #pragma unroll
            for (int mt = 0; mt < 4; mt++)
                ldsm4(a[mt], aaddr(As, AST, wm + mt * 16, kk, lane));
            #pragma unroll
            for (int p = 0; p < 2; p++) {
                u32 bb[4];
                ldsm4t(bb, baddr_t(Ws, WST, kk, wn + 16 * p, lane));
                b[2*p][0] = bb[0]; b[2*p][1] = bb[1];
                b[2*p+1][0] = bb[2]; b[2*p+1][1] = bb[3];
            }
            #pragma unroll
            for (int mt = 0; mt < 4; mt++)
                #pragma unroll
                for (int nt = 0; nt < 4; nt++) mma16(acc[mt][nt], a[mt], b[nt]);
        }
    }
}

// QKV: z picks {q,k,v}; bf16 output in [BH, N, DH] layout, bias fused.
// For z<2 the epilogue also computes exact per-head-row ||.||^2 * L2E2.
__global__ void __launch_bounds__(256) qkv_mma_kernel(
    const float* __restrict__ bq, const float* __restrict__ bk,
    const float* __restrict__ bv)
{
    extern __shared__ char smraw[];
    float* bs  = (float*)(smraw + GBS);
    float* q2p = (float*)(smraw + Q2P);   // [row][head_local][half]
    const bf16* W = g_wb[blockIdx.z];
    const float* bias = (blockIdx.z == 0) ? bq : (blockIdx.z == 1) ? bk : bv;
    bf16* O = (blockIdx.z == 0) ? g_q : (blockIdx.z == 1) ? g_k : g_v;

    const int t = threadIdx.x, lane = t & 31, wid = t >> 5;
    const int gid = lane >> 2, tig = lane & 3;
    const int wm = (wid >> 2) * 64, wn = (wid & 3) * 32;
    const int m0 = blockIdx.y * 128, n0 = blockIdx.x * 128;
    if (t < 128) bs[t] = bias[n0 + t];

    float acc[4][4][4];
    gemm_pipe_body(g_h, W, acc, smraw);

    float rp[4][2];
    #pragma unroll
    for (int mt = 0; mt < 4; mt++) { rp[mt][0] = 0.f; rp[mt][1] = 0.f; }

    #pragma unroll
    for (int mt = 0; mt < 4; mt++)
        #pragma unroll
        for (int nt = 0; nt < 4; nt++) {
            int cl = wn + nt * 8 + 2 * tig;
            int n  = n0 + cl;
            int h  = n >> 6, dh = n & 63;
            int mr = m0 + wm + mt * 16 + gid;
            {
                int b0i = mr >> 10, ns = mr & 1023;
                bf162 v = __floats2bfloat162_rn(acc[mt][nt][0] + bs[cl],
                                                acc[mt][nt][1] + bs[cl + 1]);
                *(u32*)(O + (((size_t)(b0i * Hn + h) * Nseq + ns) * DH + dh)) = *(u32*)&v;
                float2 f = b2f(*(u32*)&v);
                rp[mt][0] += f.x * f.x + f.y * f.y;
            }
            {
                int mr2 = mr + 8;
                int b0i = mr2 >> 10, ns = mr2 & 1023;
                bf162 v = __floats2bfloat162_rn(acc[mt][nt][2] + bs[cl],
                                                acc[mt][nt][3] + bs[cl + 1]);
                *(u32*)(O + (((size_t)(b0i * Hn + h) * Nseq + ns) * DH + dh)) = *(u32*)&v;
                float2 f = b2f(*(u32*)&v);
                rp[mt][1] += f.x * f.x + f.y * f.y;
            }
        }

    if (blockIdx.z < 2) {
        int hl = wn >> 6, half = (wn >> 5) & 1;
        #pragma unroll
        for (int mt = 0; mt < 4; mt++) {
            float v0 = rp[mt][0], v1 = rp[mt][1];
            v0 += __shfl_xor_sync(0xffffffffu, v0, 1);
            v0 += __shfl_xor_sync(0xffffffffu, v0, 2);
            v1 += __shfl_xor_sync(0xffffffffu, v1, 1);
            v1 += __shfl_xor_sync(0xffffffffu, v1, 2);
            if (tig == 0) {
                int rl = wm + mt * 16 + gid;
                q2p[(rl * 2 + hl) * 2 + half]       = v0;
                q2p[((rl + 8) * 2 + hl) * 2 + half] = v1;
            }
        }
        __syncthreads();
        float* dst = (blockIdx.z == 0) ? g_q2 : g_k2;
        if (t < 128) {
            int m = m0 + t;
            int b0i = m >> 10, ns = m & 1023;
            int h0 = n0 >> 6;
            #pragma unroll
            for (int hl2 = 0; hl2 < 2; hl2++) {
                float s = (q2p[(t * 2 + hl2) * 2 + 0] + q2p[(t * 2 + hl2) * 2 + 1]) * L2E2;
                dst[(size_t)(b0i * Hn + h0 + hl2) * Nseq + ns] = s;
            }
        }
    }
}

// Output projection: g_y = attnout @ Wo + bo + x   (bf16 A, f32 out)
__global__ void __launch_bounds__(256) proj_mma_kernel(
    const float* __restrict__ bo, const float* __restrict__ xres)
{
    extern __shared__ char smraw[];
    float* bs = (float*)(smraw + GBS);
    const int t = threadIdx.x, lane = t & 31, wid = t >> 5;
    const int gid = lane >> 2, tig = lane & 3;
    const int wm = (wid >> 2) * 64, wn = (wid & 3) * 32;
    const int m0 = blockIdx.y * 128, n0 = blockIdx.x * 128;
    if (t < 128) bs[t] = bo[n0 + t];

    float acc[4][4][4];
    gemm_pipe_body(g_attnout, g_wb[3], acc, smraw);

    #pragma unroll
    for (int mt = 0; mt < 4; mt++)
        #pragma unroll
        for (int nt = 0; nt < 4; nt++) {
            int cl = wn + nt * 8 + 2 * tig;
            int n  = n0 + cl;
            int mr = m0 + wm + mt * 16 + gid;
            {
                size_t idx = (size_t)mr * Ddim + n;
                float2 xr = *(const float2*)(xres + idx);
                float2 p = { acc[mt][nt][0] + bs[cl] + xr.x,
                             acc[mt][nt][1] + bs[cl + 1] + xr.y };
                *(float2*)(g_y + idx) = p;
            }
            {
                size_t idx = (size_t)(mr + 8) * Ddim + n;
                float2 xr = *(const float2*)(xres + idx);
                float2 p = { acc[mt][nt][2] + bs[cl] + xr.x,
                             acc[mt][nt][3] + bs[cl + 1] + xr.y };
                *(float2*)(g_y + idx) = p;
            }
        }
}

// ---------------- Fused attention: register-resident P, mma row-sums ----------
// Row sums computed by the tensor core: Vs padding col 64 = 1.0 (cols 65-71 = 0,
// cp.async never touches cols >= 64), one extra n-tile ldsm4t at col 56 reuses
// its upper half (cols 64-71) as the B operand of a 5th PV mma into lacc.
// lacc c0/c2 at tig==0 are the row sums; quad-broadcast at the end.
#define FAST 72
#define QS_B   0
#define KS0_B  18432
#define KS1_B  27648
#define VS0_B  36864
#define VS1_B  46080
#define K20_B  55296
#define K21_B  55552
#define FA_SMEM 55808

__global__ void __launch_bounds__(256, 2) fused_attn_kernel()
{
    extern __shared__ char smraw[];
    bf16*  Qs     = (bf16*)(smraw + QS_B);
    bf16*  Ksb[2] = { (bf16*)(smraw + KS0_B), (bf16*)(smraw + KS1_B) };
    bf16*  Vsb[2] = { (bf16*)(smraw + VS0_B), (bf16*)(smraw + VS1_B) };
    float* k2b[2] = { (float*)(smraw + K20_B), (float*)(smraw + K21_B) };

    const int t = threadIdx.x, lane = t & 31, wid = t >> 5;
    const int gid = lane >> 2, tig = lane & 3;
    const int wm = wid * 16;
    const int i0 = blockIdx.x * 128;
    const int bh = blockIdx.y;
    const bf16* Qg = g_q + (size_t)bh * Nseq * DH;
    const bf16* Kg = g_k + (size_t)bh * Nseq * DH;
    const bf16* Vg = g_v + (size_t)bh * Nseq * DH;
    const float* k2g = g_k2 + (size_t)bh * Nseq;

    // prefetch chunk 0 (K, V, k2)
    #pragma unroll
    for (int i = 0; i < 2; i++) {
        int f = t + 256 * i;
        int r = f >> 3, c = (f & 7) * 8;
        cpa16(s2u(Ksb[0] + r * FAST + c), Kg + (size_t)r * DH + c);
        cpa16(s2u(Vsb[0] + r * FAST + c), Vg + (size_t)r * DH + c);
    }
    if (t < 16) cpa16(s2u(k2b[0] + t * 4), k2g + t * 4);
    CP_COMMIT();

    // init V padding (both buffers): col 64 = 1.0 bf16, cols 65-71 = 0.
    // cp.async writes only cols 0-63, so this persists across all chunks.
    if (t < 128) {
        int buf = t >> 6, r = t & 63;
        u32* Vp = (u32*)(Vsb[buf] + r * FAST + 64);
        Vp[0] = 0x00003F80u;   // bf16 {1.0, 0.0}
        Vp[1] = 0u; Vp[2] = 0u; Vp[3] = 0u;
    }

    // load Q tile, then hoist this warp's Q A-fragments into registers
    #pragma unroll
    for (int i = 0; i < 4; i++) {
        int f = t + 256 * i;
        int r = f >> 3, c = (f & 7) * 8;
        *(uint4*)(Qs + r * FAST + c) = *(const uint4*)(Qg + (size_t)(i0 + r) * DH + c);
    }
    const float q2a = g_q2[(size_t)bh * Nseq + i0 + wm + gid];
    const float q2b = g_q2[(size_t)bh * Nseq + i0 + wm + gid + 8];
    __syncthreads();                 // Qs + V padding visible to all warps
    u32 qa[4][4];
    #pragma unroll
    for (int ks = 0; ks < 4; ks++)
        ldsm4(qa[ks], aaddr(Qs, FAST, wm, ks * 16, lane));

    float oacc[8][4];
    #pragma unroll
    for (int nt = 0; nt < 8; nt++)
        #pragma unroll
        for (int c = 0; c < 4; c++) oacc[nt][c] = 0.f;
    float lacc[4] = { 0.f, 0.f, 0.f, 0.f };

    #pragma unroll 2
    for (int jc = 0; jc < 16; jc++) {
        bf16*  Ks  = Ksb[jc & 1];
        bf16*  Vs  = Vsb[jc & 1];
        float* k2c = k2b[jc & 1];
        CP_WAIT0();
        __syncthreads();   // chunk data visible; all warps done with other buffer
        if (jc < 15) {
            int j1 = (jc + 1) * 64;
            bf16*  Kn  = Ksb[(jc + 1) & 1];
            bf16*  Vn  = Vsb[(jc + 1) & 1];
            float* k2n = k2b[(jc + 1) & 1];
            #pragma unroll
            for (int i = 0; i < 2; i++) {
                int f = t + 256 * i;
                int r = f >> 3, c = (f & 7) * 8;
                cpa16(s2u(Kn + r * FAST + c), Kg + (size_t)(j1 + r) * DH + c);
                cpa16(s2u(Vn + r * FAST + c), Vg + (size_t)(j1 + r) * DH + c);
            }
            if (t < 16) cpa16(s2u(k2n + t * 4), k2g + j1 + t * 4);
            CP_COMMIT();
        }

        // S = Q @ K^T : warp tile 16 rows x 64 keys (Q frags from registers)
        float sacc[8][4];
        #pragma unroll
        for (int nt = 0; nt < 8; nt++)
            #pragma unroll
            for (int c = 0; c < 4; c++) sacc[nt][c] = 0.f;
        #pragma unroll
        for (int ks = 0; ks < 4; ks++) {
            int kk = ks * 16;
            #pragma unroll
            for (int p = 0; p < 4; p++) {
                u32 bb[4];
                ldsm4(bb, baddr_k(Ks, FAST, 16 * p, kk, lane));
                mma16(sacc[2*p],     qa[ks], &bb[0]);
                mma16(sacc[2*p + 1], qa[ks], &bb[2]);
            }
        }

        // epilogue: P = ex2(-sqrt(d')) directly into PV A-fragments
        u32 pa[4][4];
        #pragma unroll
        for (int nt = 0; nt < 8; nt++) {
            int cl = nt * 8 + 2 * tig;
            float2 kk2 = *(const float2*)(k2c + cl);   // LDS.64
            float d0 = fmaxf(fmaf(NEG2L2, sacc[nt][0], q2a + kk2.x), EPS_SC);
            float d1 = fmaxf(fmaf(NEG2L2, sacc[nt][1], q2a + kk2.y), EPS_SC);
            float d2 = fmaxf(fmaf(NEG2L2, sacc[nt][2], q2b + kk2.x), EPS_SC);
            float d3 = fmaxf(fmaf(NEG2L2, sacc[nt][3], q2b + kk2.y), EPS_SC);
            float p0 = ex2_ap(-sqrt_ap(d0));
            float p1 = ex2_ap(-sqrt_ap(d1));
            float p2 = ex2_ap(-sqrt_ap(d2));
            float p3 = ex2_ap(-sqrt_ap(d3));
            bf162 w01 = __floats2bfloat162_rn(p0, p1);
            bf162 w23 = __floats2bfloat162_rn(p2, p3);
            if ((nt & 1) == 0) { pa[nt >> 1][0] = *(u32*)&w01; pa[nt >> 1][1] = *(u32*)&w23; }
            else               { pa[nt >> 1][2] = *(u32*)&w01; pa[nt >> 1][3] = *(u32*)&w23; }
        }

        // O += P @ V ; row sums ride a 5th n-tile (V ones column)
        #pragma unroll
        for (int k4 = 0; k4 < 4; k4++) {
            int kk = k4 * 16;
            #pragma unroll
            for (int p = 0; p < 4; p++) {
                u32 bb[4];
                ldsm4t(bb, baddr_t(Vs, FAST, kk, 16 * p, lane));
                mma16(oacc[2*p],     pa[k4], &bb[0]);
                mma16(oacc[2*p + 1], pa[k4], &bb[2]);
            }
            u32 cc[4];
            ldsm4t(cc, baddr_t(Vs, FAST, kk, 56, lane));   // cols 56-71
            mma16(lacc, pa[k4], &cc[2]);                   // cols 64-71 (ones at 64)
        }
    }

    // row sums live in tig==0's lacc[0]/lacc[2]; broadcast within each quad
    float rsum0 = __shfl_sync(0xffffffffu, lacc[0], lane & ~3);
    float rsum1 = __shfl_sync(0xffffffffu, lacc[2], lane & ~3);
    float li0 = 1.0f / rsum0;
    float li1 = 1.0f / rsum1;

    const int b = bh >> 3, h = bh & 7;
    const int i = i0 + wm + gid;
    #pragma unroll
    for (int nt = 0; nt < 8; nt++) {
        int dh = nt * 8 + 2 * tig;
        bf162 w0 = __floats2bfloat162_rn(oacc[nt][0] * li0, oacc[nt][1] * li0);
        bf162 w1 = __floats2bfloat162_rn(oacc[nt][2] * li1, oacc[nt][3] * li1);
        *(u32*)(g_attnout + ((size_t)(b * Nseq + i) * Ddim + h * DH + dh)) = *(u32*)&w0;
        *(u32*)(g_attnout + ((size_t)(b * Nseq + i + 8) * Ddim + h * DH + dh)) = *(u32*)&w1;
    }
}

// ---------------- launch ------------------------------------------------------
extern "C" void kernel_launch(void* const* d_in, const int* in_sizes, int n_in,
                              void* d_out, int out_size)
{
    const float* x = nullptr;
    const float* Wm[4] = {nullptr, nullptr, nullptr, nullptr};
    const float* vec[8] = {nullptr};
    int nm = 0, nv = 0;
    for (int i = 0; i < n_in; i++) {
        if (in_sizes[i] == BN_ROWS * Ddim)      x = (const float*)d_in[i];
        else if (in_sizes[i] == Ddim * Ddim)    { if (nm < 4) Wm[nm++] = (const float*)d_in[i]; }
        else if (in_sizes[i] == Ddim)           { if (nv < 8) vec[nv++] = (const float*)d_in[i]; }
    }
    const float *bq = vec[0], *bk = vec[1], *bv = vec[2], *bo = vec[3];
    const float *ln1g = vec[4], *ln1b = vec[5], *ln2g = vec[6], *ln2b = vec[7];

    void *p_h = nullptr, *p_y = nullptr;
    cudaGetSymbolAddress(&p_h, g_h);
    cudaGetSymbolAddress(&p_y, g_y);

    cudaFuncSetAttribute(fused_attn_kernel,
                         cudaFuncAttributeMaxDynamicSharedMemorySize, FA_SMEM);
    cudaFuncSetAttribute(qkv_mma_kernel,
                         cudaFuncAttributeMaxDynamicSharedMemorySize, GEMM_SMEM);
    cudaFuncSetAttribute(proj_mma_kernel,
                         cudaFuncAttributeMaxDynamicSharedMemorySize, GEMM_SMEM);

    wconv_kernel<<<dim3(256, 4), 256>>>(Wm[0], Wm[1], Wm[2], Wm[3]);
    ln_bf16_kernel<<<BN_ROWS / 8, 256>>>(x, ln1g, ln1b, (bf16*)p_h);
    qkv_mma_kernel<<<dim3(Ddim / 128, BN_ROWS / 128, 3), 256, GEMM_SMEM>>>(bq, bk, bv);
    fused_attn_kernel<<<dim3(Nseq / 128, NBH), 256, FA_SMEM>>>();
    proj_mma_kernel<<<dim3(Ddim / 128, BN_ROWS / 128), 256, GEMM_SMEM>>>(bo, x);
    ln_f32_kernel<<<BN_ROWS / 8, 256>>>((const float*)p_y, ln2g, ln2b, (float*)d_out);
}

// round 17
// speedup vs baseline: 1.0263x; 1.0263x over previous
#include <cuda_runtime.h>
#include <cuda_bf16.h>
#include <stdint.h>
#include <cstdint>
#include <math.h>

#define Bdim 8
#define Nseq 1024
#define Ddim 512
#define Hn 8
#define DH 64
#define BN_ROWS (Bdim * Nseq)   // 8192
#define NBH (Bdim * Hn)         // 64
#define HROWS (NBH * Nseq)      // 65536 head-rows of DH

#define L2E2 2.0813689810056077f        // (log2 e)^2
#define NEG2L2 (-2.0f * L2E2)
#define EPS_SC (1e-8f * L2E2)

typedef unsigned int u32;
typedef __nv_bfloat16 bf16;
typedef __nv_bfloat162 bf162;

// ---------------- scratch (device globals; no allocation allowed) ------------
__device__ bf16  g_h[BN_ROWS * Ddim];        // LN1 output (bf16)
__device__ bf16  g_q[BN_ROWS * Ddim];        // [BH, N, DH] bf16
__device__ bf16  g_k[BN_ROWS * Ddim];
__device__ bf16  g_v[BN_ROWS * Ddim];
__device__ bf16  g_attnout[BN_ROWS * Ddim];  // [B, N, D] bf16
__device__ float g_y[BN_ROWS * Ddim];        // proj + residual, pre-LN2 (f32)
__device__ bf16  g_wb[4][Ddim * Ddim];       // bf16 copies of Wq,Wk,Wv,Wo
__device__ float g_q2[HROWS];                // ||q||^2 * L2E2 per head-row
__device__ float g_k2[HROWS];                // ||k||^2 * L2E2 per head-row

// ---------------- helpers -----------------------------------------------------
__device__ __forceinline__ u32 s2u(const void* p) {
    u32 a;
    asm("{ .reg .u64 t; cvta.to.shared.u64 t, %1; cvt.u32.u64 %0, t; }" : "=r"(a) : "l"(p));
    return a;
}
__device__ __forceinline__ void cpa16(u32 smem, const void* g) {
    asm volatile("cp.async.cg.shared.global [%0],[%1],16;" :: "r"(smem), "l"(g));
}
#define CP_COMMIT() asm volatile("cp.async.commit_group;")
#define CP_WAIT0()  asm volatile("cp.async.wait_group 0;")
#define CP_WAIT1()  asm volatile("cp.async.wait_group 1;")

__device__ __forceinline__ void ldsm4(u32* r, u32 addr) {
    asm volatile("ldmatrix.sync.aligned.m8n8.x4.shared.b16 {%0,%1,%2,%3},[%4];"
                 : "=r"(r[0]), "=r"(r[1]), "=r"(r[2]), "=r"(r[3]) : "r"(addr));
}
__device__ __forceinline__ void ldsm4t(u32* r, u32 addr) {
    asm volatile("ldmatrix.sync.aligned.m8n8.x4.trans.shared.b16 {%0,%1,%2,%3},[%4];"
                 : "=r"(r[0]), "=r"(r[1]), "=r"(r[2]), "=r"(r[3]) : "r"(addr));
}
__device__ __forceinline__ void mma16(float* c, const u32* a, const u32* b) {
    asm volatile(
        "mma.sync.aligned.m16n8k16.row.col.f32.bf16.bf16.f32 "
        "{%0,%1,%2,%3},{%4,%5,%6,%7},{%8,%9},{%0,%1,%2,%3};\n"
        : "+f"(c[0]), "+f"(c[1]), "+f"(c[2]), "+f"(c[3])
        : "r"(a[0]), "r"(a[1]), "r"(a[2]), "r"(a[3]), "r"(b[0]), "r"(b[1]));
}
__device__ __forceinline__ u32 aaddr(const bf16* base, int stride, int mm, int k, int lane) {
    int row = mm + (lane & 7) + (((lane >> 3) & 1) << 3);
    int col = k + ((lane >> 4) << 3);
    return s2u(base + row * stride + col);
}
__device__ __forceinline__ u32 baddr_k(const bf16* base, int stride, int n, int k, int lane) {
    int m = lane >> 3;
    int row = n + ((m >> 1) << 3) + (lane & 7);
    int col = k + ((m & 1) << 3);
    return s2u(base + row * stride + col);
}
__device__ __forceinline__ u32 baddr_t(const bf16* base, int stride, int k, int n, int lane) {
    int m = lane >> 3;
    int row = k + ((m & 1) << 3) + (lane & 7);
    int col = n + ((m >> 1) << 3);
    return s2u(base + row * stride + col);
}
__device__ __forceinline__ float2 b2f(u32 u) {
    bf162 h = *(bf162*)&u;
    return __bfloat1622float2(h);
}
__device__ __forceinline__ float sqrt_ap(float x) {
    float y;
    asm("sqrt.approx.f32 %0, %1;" : "=f"(y) : "f"(x));
    return y;
}
__device__ __forceinline__ float ex2_ap(float x) {
    float y;
    asm("ex2.approx.ftz.f32 %0, %1;" : "=f"(y) : "f"(x));
    return y;
}

// ---------------- weight f32->bf16 conversion ---------------------------------
__global__ void wconv_kernel(const float* __restrict__ w0, const float* __restrict__ w1,
                             const float* __restrict__ w2, const float* __restrict__ w3)
{
    const float* src = (blockIdx.y == 0) ? w0 : (blockIdx.y == 1) ? w1
                      : (blockIdx.y == 2) ? w2 : w3;
    bf16* dst = g_wb[blockIdx.y];
    int i = blockIdx.x * 256 + threadIdx.x;
    float4 v = ((const float4*)src)[i];
    bf162 lo = __floats2bfloat162_rn(v.x, v.y);
    bf162 hi = __floats2bfloat162_rn(v.z, v.w);
    uint2 pk = { *(u32*)&lo, *(u32*)&hi };
    ((uint2*)dst)[i] = pk;
}

// ---------------- LayerNorm: one WARP per row, shuffle-only reduction ----------
__device__ __forceinline__ void ln_warp_body(const float* __restrict__ in,
                                             const float* __restrict__ gamma,
                                             const float* __restrict__ beta,
                                             int row, int lane, float4 o[4])
{
    const float4* r = (const float4*)(in + (size_t)row * Ddim);
    float4 a[4];
    float s = 0.f, s2 = 0.f;
    #pragma unroll
    for (int i = 0; i < 4; i++) {
        a[i] = r[i * 32 + lane];
        s  += a[i].x + a[i].y + a[i].z + a[i].w;
        s2 += a[i].x*a[i].x + a[i].y*a[i].y + a[i].z*a[i].z + a[i].w*a[i].w;
    }
    #pragma unroll
    for (int off = 16; off; off >>= 1) {
        s  += __shfl_xor_sync(0xffffffffu, s,  off);
        s2 += __shfl_xor_sync(0xffffffffu, s2, off);
    }
    float mean = s * (1.0f / Ddim);
    float var  = s2 * (1.0f / Ddim) - mean * mean;
    float rstd = rsqrtf(var + 1e-5f);
    #pragma unroll
    for (int i = 0; i < 4; i++) {
        float4 g = ((const float4*)gamma)[i * 32 + lane];
        float4 b = ((const float4*)beta)[i * 32 + lane];
        o[i].x = (a[i].x - mean) * rstd * g.x + b.x;
        o[i].y = (a[i].y - mean) * rstd * g.y + b.y;
        o[i].z = (a[i].z - mean) * rstd * g.z + b.z;
        o[i].w = (a[i].w - mean) * rstd * g.w + b.w;
    }
}

__global__ void __launch_bounds__(256) ln_bf16_kernel(
    const float* __restrict__ in, const float* __restrict__ gamma,
    const float* __restrict__ beta, bf16* __restrict__ out)
{
    int lane = threadIdx.x & 31;
    int row = blockIdx.x * 8 + (threadIdx.x >> 5);
    float4 o[4];
    ln_warp_body(in, gamma, beta, row, lane, o);
    #pragma unroll
    for (int i = 0; i < 4; i++) {
        bf162 lo = __floats2bfloat162_rn(o[i].x, o[i].y);
        bf162 hi = __floats2bfloat162_rn(o[i].z, o[i].w);
        uint2 pk = { *(u32*)&lo, *(u32*)&hi };
        *(uint2*)(out + (size_t)row * Ddim + (i * 32 + lane) * 4) = pk;
    }
}

__global__ void __launch_bounds__(256) ln_f32_kernel(
    const float* __restrict__ in, const float* __restrict__ gamma,
    const float* __restrict__ beta, float* __restrict__ out)
{
    int lane = threadIdx.x & 31;
    int row = blockIdx.x * 8 + (threadIdx.x >> 5);
    float4 o[4];
    ln_warp_body(in, gamma, beta, row, lane, o);
    #pragma unroll
    for (int i = 0; i < 4; i++)
        ((float4*)(out + (size_t)row * Ddim))[i * 32 + lane] = o[i];
}

// ---------------- bf16 MMA GEMM core, cp.async 3-stage pipeline ---------------
#define AST 72
#define WST 136
#define STG_A 18432                    // bytes per A stage
#define STG_W 17408                    // bytes per W stage
#define STG   (STG_A + STG_W)          // 35840
#define GBS   (3 * STG)                // 107520: bias
#define Q2P   (GBS + 512)              // 108032: q2 partials
#define GEMM_SMEM 110080

__device__ __forceinline__ void gemm_load_stage(const bf16* __restrict__ A,
                                                const bf16* __restrict__ W,
                                                bf16* As, bf16* Ws,
                                                int m0, int n0, int k0, int t)
{
    #pragma unroll
    for (int i = 0; i < 4; i++) {
        int f = t + 256 * i;
        int r = f >> 3, c = (f & 7) * 8;
        cpa16(s2u(As + r * AST + c), A + (size_t)(m0 + r) * Ddim + k0 + c);
    }
    #pragma unroll
    for (int i = 0; i < 4; i++) {
        int f = t + 256 * i;
        int r = f >> 4, c = (f & 15) * 8;
        cpa16(s2u(Ws + r * WST + c), W + (size_t)(k0 + r) * Ddim + n0 + c);
    }
    CP_COMMIT();
}

__device__ __forceinline__ void gemm_pipe_body(const bf16* __restrict__ A,
                                               const bf16* __restrict__ W,
                                               float acc[4][4][4],
                                               char* smraw)
{
    bf16* Asb[3] = { (bf16*)(smraw + 0 * STG), (bf16*)(smraw + 1 * STG),
                     (bf16*)(smraw + 2 * STG) };
    bf16* Wsb[3] = { (bf16*)(smraw + 0 * STG + STG_A), (bf16*)(smraw + 1 * STG + STG_A),
                     (bf16*)(smraw + 2 * STG + STG_A) };
    const int t = threadIdx.x, lane = t & 31, wid = t >> 5;
    const int wm = (wid >> 2) * 64, wn = (wid & 3) * 32;
    const int m0 = blockIdx.y * 128, n0 = blockIdx.x * 128;

    #pragma unroll
    for (int i = 0; i < 4; i++)
        #pragma unroll
        for (int j = 0; j < 4; j++)
            #pragma unroll
            for (int c = 0; c < 4; c++) acc[i][j][c] = 0.f;

    gemm_load_stage(A, W, Asb[0], Wsb[0], m0, n0, 0, t);
    gemm_load_stage(A, W, Asb[1], Wsb[1], m0, n0, 64, t);

    #pragma unroll
    for (int kc = 0; kc < 8; kc++) {
        bf16* As = Asb[kc % 3];
        bf16* Ws = Wsb[kc % 3];
        CP_WAIT1();        // stage kc complete (<=1 group pending)
        __syncthreads();   // visible to all; prev compute of kc-1 done everywhere
        if (kc < 6)
            gemm_load_stage(A, W, Asb[(kc + 2) % 3], Wsb[(kc + 2) % 3],
                            m0, n0, (kc + 2) * 64, t);
        #pragma unroll
        for (int ks = 0; ks < 4; ks++) {
            int kk = ks * 16;
            u32 a[4][4], b[4][2];
            #pragma unroll
            for (int mt = 0; mt < 4; mt++)
                ldsm4(a[mt], aaddr(As, AST, wm + mt * 16, kk, lane));
            #pragma unroll
            for (int p = 0; p < 2; p++) {
                u32 bb[4];
                ldsm4t(bb, baddr_t(Ws, WST, kk, wn + 16 * p, lane));
                b[2*p][0] = bb[0]; b[2*p][1] = bb[1];
                b[2*p+1][0] = bb[2]; b[2*p+1][1] = bb[3];
            }
            #pragma unroll
            for (int mt = 0; mt < 4; mt++)
                #pragma unroll
                for (int nt = 0; nt < 4; nt++) mma16(acc[mt][nt], a[mt], b[nt]);
        }
    }
    CP_WAIT0();            // drain (tail stages when kc>=6 issued nothing)
}

// QKV: z picks {q,k,v}; bf16 output in [BH, N, DH] layout, bias fused.
// For z<2 the epilogue also computes exact per-head-row ||.||^2 * L2E2.
__global__ void __launch_bounds__(256) qkv_mma_kernel(
    const float* __restrict__ bq, const float* __restrict__ bk,
    const float* __restrict__ bv)
{
    extern __shared__ char smraw[];
    float* bs  = (float*)(smraw + GBS);
    float* q2p = (float*)(smraw + Q2P);   // [row][head_local][half]
    const bf16* W = g_wb[blockIdx.z];
    const float* bias = (blockIdx.z == 0) ? bq : (blockIdx.z == 1) ? bk : bv;
    bf16* O = (blockIdx.z == 0) ? g_q : (blockIdx.z == 1) ? g_k : g_v;

    const int t = threadIdx.x, lane = t & 31, wid = t >> 5;
    const int gid = lane >> 2, tig = lane & 3;
    const int wm = (wid >> 2) * 64, wn = (wid & 3) * 32;
    const int m0 = blockIdx.y * 128, n0 = blockIdx.x * 128;
    if (t < 128) bs[t] = bias[n0 + t];

    float acc[4][4][4];
    gemm_pipe_body(g_h, W, acc, smraw);

    float rp[4][2];
    #pragma unroll
    for (int mt = 0; mt < 4; mt++) { rp[mt][0] = 0.f; rp[mt][1] = 0.f; }

    #pragma unroll
    for (int mt = 0; mt < 4; mt++)
        #pragma unroll
        for (int nt = 0; nt < 4; nt++) {
            int cl = wn + nt * 8 + 2 * tig;
            int n  = n0 + cl;
            int h  = n >> 6, dh = n & 63;
            int mr = m0 + wm + mt * 16 + gid;
            {
                int b0i = mr >> 10, ns = mr & 1023;
                bf162 v = __floats2bfloat162_rn(acc[mt][nt][0] + bs[cl],
                                                acc[mt][nt][1] + bs[cl + 1]);
                *(u32*)(O + (((size_t)(b0i * Hn + h) * Nseq + ns) * DH + dh)) = *(u32*)&v;
                float2 f = b2f(*(u32*)&v);
                rp[mt][0] += f.x * f.x + f.y * f.y;
            }
            {
                int mr2 = mr + 8;
                int b0i = mr2 >> 10, ns = mr2 & 1023;
                bf162 v = __floats2bfloat162_rn(acc[mt][nt][2] + bs[cl],
                                                acc[mt][nt][3] + bs[cl + 1]);
                *(u32*)(O + (((size_t)(b0i * Hn + h) * Nseq + ns) * DH + dh)) = *(u32*)&v;
                float2 f = b2f(*(u32*)&v);
                rp[mt][1] += f.x * f.x + f.y * f.y;
            }
        }

    if (blockIdx.z < 2) {
        int hl = wn >> 6, half = (wn >> 5) & 1;
        #pragma unroll
        for (int mt = 0; mt < 4; mt++) {
            float v0 = rp[mt][0], v1 = rp[mt][1];
            v0 += __shfl_xor_sync(0xffffffffu, v0, 1);
            v0 += __shfl_xor_sync(0xffffffffu, v0, 2);
            v1 += __shfl_xor_sync(0xffffffffu, v1, 1);
            v1 += __shfl_xor_sync(0xffffffffu, v1, 2);
            if (tig == 0) {
                int rl = wm + mt * 16 + gid;
                q2p[(rl * 2 + hl) * 2 + half]       = v0;
                q2p[((rl + 8) * 2 + hl) * 2 + half] = v1;
            }
        }
        __syncthreads();
        float* dst = (blockIdx.z == 0) ? g_q2 : g_k2;
        if (t < 128) {
            int m = m0 + t;
            int b0i = m >> 10, ns = m & 1023;
            int h0 = n0 >> 6;
            #pragma unroll
            for (int hl2 = 0; hl2 < 2; hl2++) {
                float s = (q2p[(t * 2 + hl2) * 2 + 0] + q2p[(t * 2 + hl2) * 2 + 1]) * L2E2;
                dst[(size_t)(b0i * Hn + h0 + hl2) * Nseq + ns] = s;
            }
        }
    }
}

// Output projection: g_y = attnout @ Wo + bo + x   (bf16 A, f32 out)
__global__ void __launch_bounds__(256) proj_mma_kernel(
    const float* __restrict__ bo, const float* __restrict__ xres)
{
    extern __shared__ char smraw[];
    float* bs = (float*)(smraw + GBS);
    const int t = threadIdx.x, lane = t & 31, wid = t >> 5;
    const int gid = lane >> 2, tig = lane & 3;
    const int wm = (wid >> 2) * 64, wn = (wid & 3) * 32;
    const int m0 = blockIdx.y * 128, n0 = blockIdx.x * 128;
    if (t < 128) bs[t] = bo[n0 + t];

    float acc[4][4][4];
    gemm_pipe_body(g_attnout, g_wb[3], acc, smraw);

    #pragma unroll
    for (int mt = 0; mt < 4; mt++)
        #pragma unroll
        for (int nt = 0; nt < 4; nt++) {
            int cl = wn + nt * 8 + 2 * tig;
            int n  = n0 + cl;
            int mr = m0 + wm + mt * 16 + gid;
            {
                size_t idx = (size_t)mr * Ddim + n;
                float2 xr = *(const float2*)(xres + idx);
                float2 p = { acc[mt][nt][0] + bs[cl] + xr.x,
                             acc[mt][nt][1] + bs[cl + 1] + xr.y };
                *(float2*)(g_y + idx) = p;
            }
            {
                size_t idx = (size_t)(mr + 8) * Ddim + n;
                float2 xr = *(const float2*)(xres + idx);
                float2 p = { acc[mt][nt][2] + bs[cl] + xr.x,
                             acc[mt][nt][3] + bs[cl + 1] + xr.y };
                *(float2*)(g_y + idx) = p;
            }
        }
}

// ---------------- Fused attention (R16, unchanged) -----------------------------
#define FAST 72
#define QS_B   0
#define KS0_B  18432
#define KS1_B  27648
#define VS0_B  36864
#define VS1_B  46080
#define K20_B  55296
#define K21_B  55552
#define FA_SMEM 55808

__global__ void __launch_bounds__(256, 2) fused_attn_kernel()
{
    extern __shared__ char smraw[];
    bf16*  Qs     = (bf16*)(smraw + QS_B);
    bf16*  Ksb[2] = { (bf16*)(smraw + KS0_B), (bf16*)(smraw + KS1_B) };
    bf16*  Vsb[2] = { (bf16*)(smraw + VS0_B), (bf16*)(smraw + VS1_B) };
    float* k2b[2] = { (float*)(smraw + K20_B), (float*)(smraw + K21_B) };

    const int t = threadIdx.x, lane = t & 31, wid = t >> 5;
    const int gid = lane >> 2, tig = lane & 3;
    const int wm = wid * 16;
    const int i0 = blockIdx.x * 128;
    const int bh = blockIdx.y;
    const bf16* Qg = g_q + (size_t)bh * Nseq * DH;
    const bf16* Kg = g_k + (size_t)bh * Nseq * DH;
    const bf16* Vg = g_v + (size_t)bh * Nseq * DH;
    const float* k2g = g_k2 + (size_t)bh * Nseq;

    // prefetch chunk 0 (K, V, k2)
    #pragma unroll
    for (int i = 0; i < 2; i++) {
        int f = t + 256 * i;
        int r = f >> 3, c = (f & 7) * 8;
        cpa16(s2u(Ksb[0] + r * FAST + c), Kg + (size_t)r * DH + c);
        cpa16(s2u(Vsb[0] + r * FAST + c), Vg + (size_t)r * DH + c);
    }
    if (t < 16) cpa16(s2u(k2b[0] + t * 4), k2g + t * 4);
    CP_COMMIT();

    // init V padding (both buffers): col 64 = 1.0 bf16, cols 65-71 = 0.
    if (t < 128) {
        int buf = t >> 6, r = t & 63;
        u32* Vp = (u32*)(Vsb[buf] + r * FAST + 64);
        Vp[0] = 0x00003F80u;   // bf16 {1.0, 0.0}
        Vp[1] = 0u; Vp[2] = 0u; Vp[3] = 0u;
    }

    // load Q tile, then hoist this warp's Q A-fragments into registers
    #pragma unroll
    for (int i = 0; i < 4; i++) {
        int f = t + 256 * i;
        int r = f >> 3, c = (f & 7) * 8;
        *(uint4*)(Qs + r * FAST + c) = *(const uint4*)(Qg + (size_t)(i0 + r) * DH + c);
    }
    const float q2a = g_q2[(size_t)bh * Nseq + i0 + wm + gid];
    const float q2b = g_q2[(size_t)bh * Nseq + i0 + wm + gid + 8];
    __syncthreads();                 // Qs + V padding visible to all warps
    u32 qa[4][4];
    #pragma unroll
    for (int ks = 0; ks < 4; ks++)
        ldsm4(qa[ks], aaddr(Qs, FAST, wm, ks * 16, lane));

    float oacc[8][4];
    #pragma unroll
    for (int nt = 0; nt < 8; nt++)
        #pragma unroll
        for (int c = 0; c < 4; c++) oacc[nt][c] = 0.f;
    float lacc[4] = { 0.f, 0.f, 0.f, 0.f };

    #pragma unroll 2
    for (int jc = 0; jc < 16; jc++) {
        bf16*  Ks  = Ksb[jc & 1];
        bf16*  Vs  = Vsb[jc & 1];
        float* k2c = k2b[jc & 1];
        CP_WAIT0();
        __syncthreads();
        if (jc < 15) {
            int j1 = (jc + 1) * 64;
            bf16*  Kn  = Ksb[(jc + 1) & 1];
            bf16*  Vn  = Vsb[(jc + 1) & 1];
            float* k2n = k2b[(jc + 1) & 1];
            #pragma unroll
            for (int i = 0; i < 2; i++) {
                int f = t + 256 * i;
                int r = f >> 3, c = (f & 7) * 8;
                cpa16(s2u(Kn + r * FAST + c), Kg + (size_t)(j1 + r) * DH + c);
                cpa16(s2u(Vn + r * FAST + c), Vg + (size_t)(j1 + r) * DH + c);
            }
            if (t < 16) cpa16(s2u(k2n + t * 4), k2g + j1 + t * 4);
            CP_COMMIT();
        }

        // S = Q @ K^T
        float sacc[8][4];
        #pragma unroll
        for (int nt = 0; nt < 8; nt++)
            #pragma unroll
            for (int c = 0; c < 4; c++) sacc[nt][c] = 0.f;
        #pragma unroll
        for (int ks = 0; ks < 4; ks++) {
            int kk = ks * 16;
            #pragma unroll
            for (int p = 0; p < 4; p++) {
                u32 bb[4];
                ldsm4(bb, baddr_k(Ks, FAST, 16 * p, kk, lane));
                mma16(sacc[2*p],     qa[ks], &bb[0]);
                mma16(sacc[2*p + 1], qa[ks], &bb[2]);
            }
        }

        // epilogue: P = ex2(-sqrt(d')) directly into PV A-fragments
        u32 pa[4][4];
        #pragma unroll
        for (int nt = 0; nt < 8; nt++) {
            int cl = nt * 8 + 2 * tig;
            float2 kk2 = *(const float2*)(k2c + cl);
            float d0 = fmaxf(fmaf(NEG2L2, sacc[nt][0], q2a + kk2.x), EPS_SC);
            float d1 = fmaxf(fmaf(NEG2L2, sacc[nt][1], q2a + kk2.y), EPS_SC);
            float d2 = fmaxf(fmaf(NEG2L2, sacc[nt][2], q2b + kk2.x), EPS_SC);
            float d3 = fmaxf(fmaf(NEG2L2, sacc[nt][3], q2b + kk2.y), EPS_SC);
            float p0 = ex2_ap(-sqrt_ap(d0));
            float p1 = ex2_ap(-sqrt_ap(d1));
            float p2 = ex2_ap(-sqrt_ap(d2));
            float p3 = ex2_ap(-sqrt_ap(d3));
            bf162 w01 = __floats2bfloat162_rn(p0, p1);
            bf162 w23 = __floats2bfloat162_rn(p2, p3);
            if ((nt & 1) == 0) { pa[nt >> 1][0] = *(u32*)&w01; pa[nt >> 1][1] = *(u32*)&w23; }
            else               { pa[nt >> 1][2] = *(u32*)&w01; pa[nt >> 1][3] = *(u32*)&w23; }
        }

        // O += P @ V ; row sums ride a 5th n-tile (V ones column)
        #pragma unroll
        for (int k4 = 0; k4 < 4; k4++) {
            int kk = k4 * 16;
            #pragma unroll
            for (int p = 0; p < 4; p++) {
                u32 bb[4];
                ldsm4t(bb, baddr_t(Vs, FAST, kk, 16 * p, lane));
                mma16(oacc[2*p],     pa[k4], &bb[0]);
                mma16(oacc[2*p + 1], pa[k4], &bb[2]);
            }
            u32 cc[4];
            ldsm4t(cc, baddr_t(Vs, FAST, kk, 56, lane));
            mma16(lacc, pa[k4], &cc[2]);
        }
    }

    float rsum0 = __shfl_sync(0xffffffffu, lacc[0], lane & ~3);
    float rsum1 = __shfl_sync(0xffffffffu, lacc[2], lane & ~3);
    float li0 = 1.0f / rsum0;
    float li1 = 1.0f / rsum1;

    const int b = bh >> 3, h = bh & 7;
    const int i = i0 + wm + gid;
    #pragma unroll
    for (int nt = 0; nt < 8; nt++) {
        int dh = nt * 8 + 2 * tig;
        bf162 w0 = __floats2bfloat162_rn(oacc[nt][0] * li0, oacc[nt][1] * li0);
        bf162 w1 = __floats2bfloat162_rn(oacc[nt][2] * li1, oacc[nt][3] * li1);
        *(u32*)(g_attnout + ((size_t)(b * Nseq + i) * Ddim + h * DH + dh)) = *(u32*)&w0;
        *(u32*)(g_attnout + ((size_t)(b * Nseq + i + 8) * Ddim + h * DH + dh)) = *(u32*)&w1;
    }
}

// ---------------- launch ------------------------------------------------------
extern "C" void kernel_launch(void* const* d_in, const int* in_sizes, int n_in,
                              void* d_out, int out_size)
{
    const float* x = nullptr;
    const float* Wm[4] = {nullptr, nullptr, nullptr, nullptr};
    const float* vec[8] = {nullptr};
    int nm = 0, nv = 0;
    for (int i = 0; i < n_in; i++) {
        if (in_sizes[i] == BN_ROWS * Ddim)      x = (const float*)d_in[i];
        else if (in_sizes[i] == Ddim * Ddim)    { if (nm < 4) Wm[nm++] = (const float*)d_in[i]; }
        else if (in_sizes[i] == Ddim)           { if (nv < 8) vec[nv++] = (const float*)d_in[i]; }
    }
    const float *bq = vec[0], *bk = vec[1], *bv = vec[2], *bo = vec[3];
    const float *ln1g = vec[4], *ln1b = vec[5], *ln2g = vec[6], *ln2b = vec[7];

    void *p_h = nullptr, *p_y = nullptr;
    cudaGetSymbolAddress(&p_h, g_h);
    cudaGetSymbolAddress(&p_y, g_y);

    cudaFuncSetAttribute(fused_attn_kernel,
                         cudaFuncAttributeMaxDynamicSharedMemorySize, FA_SMEM);
    cudaFuncSetAttribute(qkv_mma_kernel,
                         cudaFuncAttributeMaxDynamicSharedMemorySize, GEMM_SMEM);
    cudaFuncSetAttribute(proj_mma_kernel,
                         cudaFuncAttributeMaxDynamicSharedMemorySize, GEMM_SMEM);

    wconv_kernel<<<dim3(256, 4), 256>>>(Wm[0], Wm[1], Wm[2], Wm[3]);
    ln_bf16_kernel<<<BN_ROWS / 8, 256>>>(x, ln1g, ln1b, (bf16*)p_h);
    qkv_mma_kernel<<<dim3(Ddim / 128, BN_ROWS / 128, 3), 256, GEMM_SMEM>>>(bq, bk, bv);
    fused_attn_kernel<<<dim3(Nseq / 128, NBH), 256, FA_SMEM>>>();
    proj_mma_kernel<<<dim3(Ddim / 128, BN_ROWS / 128), 256, GEMM_SMEM>>>(bo, x);
    ln_f32_kernel<<<BN_ROWS / 8, 256>>>((const float*)p_y, ln2g, ln2b, (float*)d_out);
}